// round 10
// baseline (speedup 1.0000x reference)
#include <cuda_runtime.h>
#include <cuda_bf16.h>

// Problem constants
#define BB    16
#define MM    127
#define PP    3
#define KLEN  132
#define NSPAN 126
#define SS    256
#define CDIM  3
#define EPSF  1e-8f

#define EVT 256      // threads per block (8 warps)
#define GPB 8        // iu per block == warps per block

// ---------------------------------------------------------------------------
// Warp-collective knot prep: lanes 0..31 cumsum KLEN=132 knots (5/lane),
// shuffle-scan lane totals, normalize in-warp, store normalized knots to sK.
// Numerics identical to the proven R5/R7 prep.
// ---------------------------------------------------------------------------
__device__ __forceinline__ void scan_knots_warp(const float* __restrict__ knots,
                                                float* __restrict__ sK,
                                                int lane)
{
    float vals[5];
    float run = 0.f;
    #pragma unroll
    for (int k = 0; k < 5; k++) {
        const int idx = lane * 5 + k;
        if (idx < KLEN) {
            float w = knots[idx];
            run += (w < 0.f) ? 1e-4f : w;
            vals[k] = run;
        }
    }
    float tot = run;
    #pragma unroll
    for (int off = 1; off < 32; off <<= 1) {
        float n = __shfl_up_sync(0xFFFFFFFFu, tot, off);
        if (lane >= off) tot += n;
    }
    const float pre = tot - run;                           // exclusive prefix
    const float k0   = __shfl_sync(0xFFFFFFFFu, vals[0], 0);
    const float kend = __shfl_sync(0xFFFFFFFFu, tot, 31);  // full cumsum
    const float inv  = 1.f / (kend - k0);
    #pragma unroll
    for (int k = 0; k < 5; k++) {
        const int idx = lane * 5 + k;
        if (idx < KLEN) sK[idx] = (vals[k] + pre - k0) * inv;
    }
}

// ---------------------------------------------------------------------------
// Span (binary search over monotone predicate == reference masked-argmin)
// + cubic Cox-de-Boor basis, reference's exact FP expression order.
// ---------------------------------------------------------------------------
__device__ __forceinline__ void span_basis(const float* __restrict__ sK,
                                           float t, int* span_out, float4* n_out)
{
    int lo = -1, hi = NSPAN;
    while (hi - lo > 1) {
        const int mid = (lo + hi) >> 1;
        if (t - sK[3 + mid] > EPSF) lo = mid; else hi = mid;
    }
    int idx = (lo < 0) ? 0 : lo;
    int span = idx + PP;
    span = (span < PP) ? PP : (span > MM ? MM : span);

    float Ni[4];
    Ni[0] = 1.f; Ni[1] = 0.f; Ni[2] = 0.f; Ni[3] = 0.f;
    #pragma unroll
    for (int k = 1; k <= PP; k++) {
        float saved = 0.f;
        #pragma unroll
        for (int r = 0; r < 3; r++) {
            if (r >= k) break;
            const float K1 = sK[span + r + 1];
            const float K2 = sK[span + 1 - k + r];
            const float denom = (K1 - t) + (t - K2);   // exact ref order
            const float temp  = (denom == 0.f) ? 1e-4f : Ni[r] / denom;
            Ni[r] = saved + (K1 - t) * temp;
            saved = (t - K2) * temp;
        }
        Ni[k] = saved;
    }
    *span_out = span;
    *n_out = make_float4(Ni[0], Ni[1], Ni[2], Ni[3]);
}

// ---------------------------------------------------------------------------
// Fused kernel, warp-autonomous design:
//  prep (2 block barriers total):
//    warps 0/1 scan u/v knots; every thread computes ONE v-basis -> smem;
//    threads 0..7 compute the block's 8 u-bases -> smem.
//  main (ZERO block barriers):
//    warp w owns iu = iug + w: 12x LDG.128 burst -> u-contract in regs ->
//    STS.128 x3 into warp-PRIVATE smem tile -> __syncwarp -> 8 passes of 32
//    points (12 LDS + 12 FMA + 3 STG), fully unrolled. Warps never wait on
//    each other, so one slow memory op stalls only its own warp.
// ---------------------------------------------------------------------------
__global__ __launch_bounds__(EVT, 4) void fused_kernel(
    const float* __restrict__ ctrl,
    const float* __restrict__ knot_u,
    const float* __restrict__ knot_v,
    const float* __restrict__ uu,
    const float* __restrict__ vv,
    float* __restrict__ out)
{
    const int bid  = blockIdx.x;            // 0 .. 511
    const int b    = bid >> 5;              // 32 blocks per batch
    const int iug  = (bid & 31) * GPB;
    const int tid  = threadIdx.x;
    const int wid  = tid >> 5;
    const int lane = tid & 31;

    __shared__ float  sKu[KLEN];
    __shared__ float  sKv[KLEN];
    __shared__ float4 s_nu[GPB];
    __shared__ int    s_us[GPB];
    __shared__ float4 s_nv[SS];             // one v-basis per iv
    __shared__ int    s_voff[SS];
    __shared__ float  sT[GPB][128 * CDIM];  // warp-private u-contracted rows

    // --- prep ---
    if (wid == 0)      scan_knots_warp(knot_u + b * KLEN, sKu, lane);
    else if (wid == 1) scan_knots_warp(knot_v + b * KLEN, sKv, lane);
    __syncthreads();

    {   // one v-basis per thread
        int vs; float4 nv;
        span_basis(sKv, vv[tid], &vs, &nv);
        s_nv[tid]   = nv;
        s_voff[tid] = (vs - 3) * CDIM;
    }
    if (tid < GPB) {                        // 8 u-bases
        int us; float4 nu;
        span_basis(sKu, uu[iug + tid], &us, &nu);
        s_nu[tid] = nu;
        s_us[tid] = us;
    }
    __syncthreads();

    // --- main: warp w handles iu = iug + wid, fully autonomous ---
    const float4 nu = s_nu[wid];
    const int    us = s_us[wid];
    const float4* cb4 = (const float4*)(ctrl + (size_t)(b * 128 + (us - 3)) * 384);

    // Load 4 rows x 3 chunks per lane (12 independent LDG.128)
    float4 r[4][3];
    #pragma unroll
    for (int p = 0; p < 4; p++)
        #pragma unroll
        for (int j = 0; j < 3; j++)
            r[p][j] = cb4[p * 96 + j * 32 + lane];

    // u-contract and store to warp-private smem tile
    float4* sTw4 = (float4*)sT[wid];
    #pragma unroll
    for (int j = 0; j < 3; j++) {
        float4 acc;
        acc.x = nu.x * r[0][j].x + nu.y * r[1][j].x + nu.z * r[2][j].x + nu.w * r[3][j].x;
        acc.y = nu.x * r[0][j].y + nu.y * r[1][j].y + nu.z * r[2][j].y + nu.w * r[3][j].y;
        acc.z = nu.x * r[0][j].z + nu.y * r[1][j].z + nu.z * r[2][j].z + nu.w * r[3][j].z;
        acc.w = nu.x * r[0][j].w + nu.y * r[1][j].w + nu.z * r[2][j].w + nu.w * r[3][j].w;
        sTw4[j * 32 + lane] = acc;
    }
    __syncwarp();

    const float* sTw = sT[wid];
    float* op = out + (((size_t)b * SS + (iug + wid)) * SS) * CDIM;

    #pragma unroll
    for (int c = 0; c < 8; c++) {
        const int iv = c * 32 + lane;
        const float4 nv  = s_nv[iv];
        const float* t0  = sTw + s_voff[iv];
        const float ax = nv.x * t0[0] + nv.y * t0[3] + nv.z * t0[6] + nv.w * t0[9];
        const float ay = nv.x * t0[1] + nv.y * t0[4] + nv.z * t0[7] + nv.w * t0[10];
        const float az = nv.x * t0[2] + nv.y * t0[5] + nv.z * t0[8] + nv.w * t0[11];
        float* o = op + (size_t)iv * CDIM;
        o[0] = ax; o[1] = ay; o[2] = az;
    }
}

// ---------------------------------------------------------------------------
// Inputs (metadata order): ctrl_pts, knot_u, knot_v, u, v. Output: float32.
// ---------------------------------------------------------------------------
extern "C" void kernel_launch(void* const* d_in, const int* in_sizes, int n_in,
                              void* d_out, int out_size)
{
    const float* ctrl   = (const float*)d_in[0];
    const float* knot_u = (const float*)d_in[1];
    const float* knot_v = (const float*)d_in[2];
    const float* uu     = (const float*)d_in[3];
    const float* vv     = (const float*)d_in[4];
    float* out = (float*)d_out;

    fused_kernel<<<BB * SS / GPB, EVT>>>(ctrl, knot_u, knot_v, uu, vv, out);
}